// round 13
// baseline (speedup 1.0000x reference)
#include <cuda_runtime.h>
#include <cuda_bf16.h>
#include <cstdint>

__device__ double             g_total = 0.0;
__device__ unsigned long long g_rows  = 0ull;
__device__ unsigned int       g_done  = 0u;

#define THREADS        256
#define BLOCKS         888          // 148 SMs * 6
#define RSTAGES        2            // ring depth (double buffer)
#define ROWS_PER_STAGE 4
#define STAGE_BYTES    (ROWS_PER_STAGE * 2 * 2048)   // emb+cen, 16KB
// dynamic smem = 2 * 16KB = 32768 B  (+ ~0.6KB static, well under 48KB cap)

// Packed f32x2 FMA (sm_103a FFMA2 — PTX-only).
__device__ __forceinline__ unsigned long long fma2(unsigned long long a,
                                                   unsigned long long b,
                                                   unsigned long long c)
{
    unsigned long long d;
    asm("fma.rn.f32x2 %0, %1, %2, %3;" : "=l"(d) : "l"(a), "l"(b), "l"(c));
    return d;
}

__device__ __forceinline__ float unpack_sum(unsigned long long v)
{
    return __int_as_float((int)(v & 0xFFFFFFFFull)) +
           __int_as_float((int)(v >> 32));
}

__device__ __forceinline__ void mbar_init(uint32_t addr, uint32_t count)
{
    asm volatile("mbarrier.init.shared.b64 [%0], %1;" :: "r"(addr), "r"(count) : "memory");
}

__device__ __forceinline__ void mbar_arrive(uint32_t addr)
{
    asm volatile("mbarrier.arrive.shared.b64 _, [%0];" :: "r"(addr) : "memory");
}

__device__ __forceinline__ void mbar_expect_tx(uint32_t addr, uint32_t bytes)
{
    asm volatile("mbarrier.arrive.expect_tx.shared.b64 _, [%0], %1;"
                 :: "r"(addr), "r"(bytes) : "memory");
}

__device__ __forceinline__ void mbar_wait(uint32_t addr, uint32_t parity)
{
    asm volatile(
        "{\n\t"
        ".reg .pred P1;\n\t"
        "WAIT_LOOP_%=:\n\t"
        "mbarrier.try_wait.parity.acquire.cta.shared::cta.b64 P1, [%0], %1, 0x989680;\n\t"
        "@P1 bra.uni WAIT_DONE_%=;\n\t"
        "bra.uni WAIT_LOOP_%=;\n\t"
        "WAIT_DONE_%=:\n\t"
        "}"
        :: "r"(addr), "r"(parity) : "memory");
}

// 1D bulk async copy global->shared (2KB row), completion via mbarrier complete_tx.
__device__ __forceinline__ void bulk_cp(uint32_t dst_smem, const void* src, uint32_t mbar)
{
    asm volatile(
        "cp.async.bulk.shared::cluster.global.mbarrier::complete_tx::bytes "
        "[%0], [%1], %2, [%3];"
        :: "r"(dst_smem), "l"(src), "r"(2048u), "r"(mbar) : "memory");
}

__global__ __launch_bounds__(THREADS)
void fused_mse_kernel(const float* __restrict__ emb,
                      const float* __restrict__ cen,
                      const int*   __restrict__ labels,
                      const int*   __restrict__ num_old_p,
                      int batch, int rows_per_block,
                      float* __restrict__ out)
{
    extern __shared__ double2 dyn[];   // [RSTAGES][1024]: 512 emb + 512 cen double2

    const int num_old = *num_old_p;

    __shared__ unsigned int s_list[128];   // packed: row | (label<<16); M <= 74
    __shared__ unsigned int s_cnt;
    __shared__ unsigned int s_warpbase[THREADS / 32];
    __shared__ double       s_total;
    __shared__ alignas(8) unsigned long long s_mbar[2 * RSTAGES];  // full[0..1], empty[2..3]

    const unsigned tid  = threadIdx.x;
    const unsigned lane = tid & 31u;

    const uint32_t mbar_base = (uint32_t)__cvta_generic_to_shared(s_mbar);
    const uint32_t dyn_base  = (uint32_t)__cvta_generic_to_shared(dyn);
    #define FULL_MB(slot)  (mbar_base + (slot) * 8u)
    #define EMPTY_MB(slot) (mbar_base + (RSTAGES + (slot)) * 8u)

    if (tid == 0) {
        s_cnt = 0u; s_total = 0.0;
        #pragma unroll
        for (int i = 0; i < RSTAGES; i++) {
            mbar_init(FULL_MB(i), 1u);                 // expect_tx arrive
            mbar_init(EMPTY_MB(i), THREADS / 32);      // one arrive per warp
        }
    }
    __syncthreads();

    // ---- Per-block compaction of this block's row slice ----
    const int row0  = blockIdx.x * rows_per_block;
    int nrows = batch - row0;
    if (nrows > rows_per_block) nrows = rows_per_block;
    if (nrows < 0) nrows = 0;

    {
        const int  wid    = tid >> 5;
        bool       active = false;
        int        label  = 0;
        const int  row    = row0 + (int)tid;
        if ((int)tid < nrows) { label = labels[row]; active = (label < num_old); }
        const unsigned mask = __ballot_sync(0xFFFFFFFFu, active);
        if (lane == 0) s_warpbase[wid] = atomicAdd(&s_cnt, (unsigned)__popc(mask));
        __syncwarp();
        if (active) {
            const unsigned pos = s_warpbase[wid] + (unsigned)__popc(mask & ((1u << lane) - 1u));
            s_list[pos] = (unsigned)row | ((unsigned)label << 16);
        }
    }
    __syncthreads();

    const unsigned M = s_cnt;                                      // active rows
    const unsigned S = (M + ROWS_PER_STAGE - 1) / ROWS_PER_STAGE;  // stages

    const unsigned long long NEG1 = 0xBF800000BF800000ull;
    unsigned long long accA = 0ull, accB = 0ull, accC = 0ull, accD = 0ull;

    // Producer: issue one stage's bulk copies into a ring slot.
    auto issue_stage = [&](unsigned t) {
        const unsigned slot = t % RSTAGES;
        unsigned m0 = M - t * ROWS_PER_STAGE;
        if (m0 > ROWS_PER_STAGE) m0 = ROWS_PER_STAGE;
        mbar_expect_tx(FULL_MB(slot), m0 * 4096u);
        const uint32_t e_dst = dyn_base + slot * STAGE_BYTES;
        const uint32_t c_dst = e_dst + ROWS_PER_STAGE * 2048u;
        for (unsigned r = 0; r < m0; r++) {
            const unsigned p = s_list[t * ROWS_PER_STAGE + r];
            bulk_cp(e_dst + r * 2048u, emb + (size_t)(p & 0xFFFFu) * 512u, FULL_MB(slot));
            bulk_cp(c_dst + r * 2048u, cen + (size_t)(p >> 16)     * 512u, FULL_MB(slot));
        }
    };

    // Prologue: fill the ring.
    if (tid == 0) {
        const unsigned pre = (S < RSTAGES) ? S : RSTAGES;
        for (unsigned t = 0; t < pre; t++) issue_stage(t);
    }

    // ---- Main loop: consume stage s; thread 0 refills slot with s+RSTAGES ----
    for (unsigned s = 0; s < S; s++) {
        const unsigned slot = s % RSTAGES;
        const unsigned par  = (s / RSTAGES) & 1u;

        mbar_wait(FULL_MB(slot), par);

        const double2* eslot = dyn + (size_t)slot * 1024u;
        const double2* cslot = eslot + 512u;
        const unsigned base_row = s * ROWS_PER_STAGE;

        // chunk c in [0,512): row_in_stage = c>>7. Thread handles c=tid, c=tid+256.
        if (base_row + (tid >> 7) < M) {
            const double2 e = eslot[tid];
            const double2 c = cslot[tid];
            unsigned long long d;
            d = fma2(__double_as_longlong(c.x), NEG1, __double_as_longlong(e.x)); accA = fma2(d, d, accA);
            d = fma2(__double_as_longlong(c.y), NEG1, __double_as_longlong(e.y)); accB = fma2(d, d, accB);
        }
        if (base_row + ((tid + 256u) >> 7) < M) {
            const double2 e = eslot[tid + 256u];
            const double2 c = cslot[tid + 256u];
            unsigned long long d;
            d = fma2(__double_as_longlong(c.x), NEG1, __double_as_longlong(e.x)); accC = fma2(d, d, accC);
            d = fma2(__double_as_longlong(c.y), NEG1, __double_as_longlong(e.y)); accD = fma2(d, d, accD);
        }

        __syncwarp();
        if (lane == 0) mbar_arrive(EMPTY_MB(slot));

        if (tid == 0 && s + RSTAGES < S) {
            // Slot frees for stage s+RSTAGES once all 8 warps arrive.
            mbar_wait(EMPTY_MB(slot), par);
            issue_stage(s + RSTAGES);
        }
    }

    // ---- Reduction ----
    float acc = unpack_sum(accA) + unpack_sum(accB) +
                unpack_sum(accC) + unpack_sum(accD);
    #pragma unroll
    for (int off = 16; off > 0; off >>= 1)
        acc += __shfl_xor_sync(0xFFFFFFFFu, acc, off);

    if (lane == 0 && acc != 0.0f)
        atomicAdd(&s_total, (double)acc);
    __syncthreads();

    if (tid == 0) {
        if (s_total != 0.0) atomicAdd(&g_total, s_total);
        if (M != 0u)        atomicAdd(&g_rows, (unsigned long long)M);
        __threadfence();
        const unsigned ticket = atomicAdd(&g_done, 1u);
        if (ticket == gridDim.x - 1u) {
            const double             t = g_total * (1.0 / 512.0);
            const unsigned long long c = g_rows;
            out[0] = (c == 0ull) ? (float)t : (float)(t / (double)c);
            g_total = 0.0;
            g_rows  = 0ull;
            g_done  = 0u;
        }
    }
    #undef FULL_MB
    #undef EMPTY_MB
}

extern "C" void kernel_launch(void* const* d_in, const int* in_sizes, int n_in,
                              void* d_out, int out_size)
{
    const float* emb       = (const float*)d_in[0];
    const float* cen       = (const float*)d_in[1];
    const int*   labels    = (const int*)d_in[2];
    const int*   num_old_p = (const int*)d_in[3];
    float*       out       = (float*)d_out;

    const int dim   = 512;
    const int batch = in_sizes[0] / dim;                        // 65536
    const int rows_per_block = (batch + BLOCKS - 1) / BLOCKS;   // 74

    const int dyn_smem = RSTAGES * STAGE_BYTES;                 // 32768 B
    fused_mse_kernel<<<BLOCKS, THREADS, dyn_smem>>>(emb, cen, labels, num_old_p,
                                                    batch, rows_per_block, out);
}